// round 3
// baseline (speedup 1.0000x reference)
#include <cuda_runtime.h>

// DeepFeatureLoss: out[b] = sum_i w[b,i] * sum_j (p_ij - q_ij)^2
//   p = softmax_j over -||x_i/s - x_j/s||^2   (scores <= 0, max at j==i)
//   q = softmax_j over -||f1_i - f2_j||^2     (scores <= 0 -> fixed 2^KSH shift, no online max)
// sum_j (p-q)^2 = B/Zp^2 - 2A/(Zp Zq) + C/Zq^2.
// Records pre-scaled by 2*log2e so both exps are bare ex2.approx.
// Main kernel: IR=2 rows per thread, j-record broadcast from shared via LDS.128.

#define SIGMA_INV 20.0f
#define LOG2E     1.4426950408889634f
#define KSH       44.0f
#define S_CHUNKS  32
#define R_ROWS    128          // threads per block
#define IR        2            // rows per thread
#define TJ        128
#define MAX_ROWS  16384

// per-j record, 10 float4 (40 floats):
// [0..31]: 2*log2e*f2
// [32..35]: (2L*u0, 2L*u1, 2L*u2, -L*|u|^2)
// [36]: -L*|f2|^2, [37..39] pad
static __device__ __align__(16) float4 g_rec[MAX_ROWS * 10];
// per (row, chunk) partial: (Zq, A, C, Zp), (Bb, 0,0,0)
static __device__ __align__(16) float4 g_part[(size_t)MAX_ROWS * S_CHUNKS * 2];

typedef unsigned long long ull;

__device__ __forceinline__ ull f2mul(ull a, ull b) {
    ull d; asm("mul.rn.f32x2 %0, %1, %2;" : "=l"(d) : "l"(a), "l"(b)); return d;
}
__device__ __forceinline__ ull f2fma(ull a, ull b, ull c) {
    ull d; asm("fma.rn.f32x2 %0, %1, %2, %3;" : "=l"(d) : "l"(a), "l"(b), "l"(c)); return d;
}
__device__ __forceinline__ ull f2add(ull a, ull b) {
    ull d; asm("add.rn.f32x2 %0, %1, %2;" : "=l"(d) : "l"(a), "l"(b)); return d;
}
__device__ __forceinline__ float ex2f(float x) {
    float y; asm("ex2.approx.f32 %0, %1;" : "=f"(y) : "f"(x)); return y;
}
__device__ __forceinline__ void unpack2(ull v, float& lo, float& hi) {
    asm("mov.b64 {%0, %1}, %2;" : "=f"(lo), "=f"(hi) : "l"(v));
}
__device__ __forceinline__ ull pack2(float lo, float hi) {
    ull v; asm("mov.b64 %0, {%1, %2};" : "=l"(v) : "f"(lo), "f"(hi)); return v;
}

__global__ void prep_kernel(const float* __restrict__ points,
                            const float* __restrict__ fea2,
                            int BN)
{
    int g = blockIdx.x * blockDim.x + threadIdx.x;
    if (g >= BN) return;

    float4 r[10];
    const float4* f2 = (const float4*)(fea2 + (size_t)g * 32);
    float cf = 0.f;
#pragma unroll
    for (int q = 0; q < 8; q++) {
        float4 v = f2[q];
        cf = fmaf(v.x, v.x, cf); cf = fmaf(v.y, v.y, cf);
        cf = fmaf(v.z, v.z, cf); cf = fmaf(v.w, v.w, cf);
        float s = 2.f * LOG2E;
        r[q] = make_float4(s * v.x, s * v.y, s * v.z, s * v.w);
    }
    float u0 = points[(size_t)g * 3 + 0] * SIGMA_INV;
    float u1 = points[(size_t)g * 3 + 1] * SIGMA_INV;
    float u2 = points[(size_t)g * 3 + 2] * SIGMA_INV;
    float cu = -(u0 * u0 + u1 * u1 + u2 * u2) * LOG2E;
    float s = 2.f * LOG2E;
    r[8] = make_float4(s * u0, s * u1, s * u2, cu);
    r[9] = make_float4(-cf * LOG2E, 0.f, 0.f, 0.f);

#pragma unroll
    for (int q = 0; q < 10; q++) g_rec[(size_t)g * 10 + q] = r[q];
}

// 16-term packed dot against w0..w7 (ulonglong2 pairs), returns lo+hi sum
__device__ __forceinline__ float dot32(const ull* rp,
                                       ull w0x, ull w0y, ull w1x, ull w1y,
                                       ull w2x, ull w2y, ull w3x, ull w3y,
                                       ull w4x, ull w4y, ull w5x, ull w5y,
                                       ull w6x, ull w6y, ull w7x, ull w7y)
{
    ull a0 = f2mul(rp[0],  w0x);
    ull a1 = f2mul(rp[1],  w0y);
    ull a2 = f2mul(rp[2],  w1x);
    ull a3 = f2mul(rp[3],  w1y);
    a0 = f2fma(rp[4],  w2x, a0);
    a1 = f2fma(rp[5],  w2y, a1);
    a2 = f2fma(rp[6],  w3x, a2);
    a3 = f2fma(rp[7],  w3y, a3);
    a0 = f2fma(rp[8],  w4x, a0);
    a1 = f2fma(rp[9],  w4y, a1);
    a2 = f2fma(rp[10], w5x, a2);
    a3 = f2fma(rp[11], w5y, a3);
    a0 = f2fma(rp[12], w6x, a0);
    a1 = f2fma(rp[13], w6y, a1);
    a2 = f2fma(rp[14], w7x, a2);
    a3 = f2fma(rp[15], w7y, a3);
    ull ss = f2add(f2add(a0, a1), f2add(a2, a3));
    float lo, hi; unpack2(ss, lo, hi);
    return lo + hi;
}

__global__ __launch_bounds__(R_ROWS, 3) void main_kernel(
    const float* __restrict__ fea1,
    const float* __restrict__ points,
    int N)
{
    __shared__ __align__(16) float4 srec[TJ * 10];

    const int rowblk = blockIdx.x / S_CHUNKS;
    const int chunk  = blockIdx.x % S_CHUNKS;
    const int gA = rowblk * (R_ROWS * IR) + threadIdx.x;   // row A
    const int gB = gA + R_ROWS;                            // row B
    const int b  = gA / N;
    const int JC = N / S_CHUNKS;
    const int j0 = b * N + chunk * JC;

    // row constants: packed features + spatial consts, per row
    ull rpA[16], rpB[16];
    float nfA = 0.f, nfB = 0.f;
    {
        const float4* fp = (const float4*)(fea1 + (size_t)gA * 32);
#pragma unroll
        for (int q = 0; q < 8; q++) {
            float4 v = fp[q];
            nfA = fmaf(v.x, v.x, nfA); nfA = fmaf(v.y, v.y, nfA);
            nfA = fmaf(v.z, v.z, nfA); nfA = fmaf(v.w, v.w, nfA);
            rpA[2 * q + 0] = pack2(v.x, v.y);
            rpA[2 * q + 1] = pack2(v.z, v.w);
        }
        fp = (const float4*)(fea1 + (size_t)gB * 32);
#pragma unroll
        for (int q = 0; q < 8; q++) {
            float4 v = fp[q];
            nfB = fmaf(v.x, v.x, nfB); nfB = fmaf(v.y, v.y, nfB);
            nfB = fmaf(v.z, v.z, nfB); nfB = fmaf(v.w, v.w, nfB);
            rpB[2 * q + 0] = pack2(v.x, v.y);
            rpB[2 * q + 1] = pack2(v.z, v.w);
        }
    }
    const float cqA = KSH - nfA * LOG2E;
    const float cqB = KSH - nfB * LOG2E;

    float uA0 = points[(size_t)gA * 3 + 0] * SIGMA_INV;
    float uA1 = points[(size_t)gA * 3 + 1] * SIGMA_INV;
    float uA2 = points[(size_t)gA * 3 + 2] * SIGMA_INV;
    const float cpA = -(uA0 * uA0 + uA1 * uA1 + uA2 * uA2) * LOG2E;
    float uB0 = points[(size_t)gB * 3 + 0] * SIGMA_INV;
    float uB1 = points[(size_t)gB * 3 + 1] * SIGMA_INV;
    float uB2 = points[(size_t)gB * 3 + 2] * SIGMA_INV;
    const float cpB = -(uB0 * uB0 + uB1 * uB1 + uB2 * uB2) * LOG2E;

    // accumulators: ZA=(Zq,Zp) packed, SA=(C,Bb) packed, A scalar — per row
    ull ZA = 0, SA = 0, ZB = 0, SB = 0;
    float AA = 0.f, AB = 0.f;

#pragma unroll 1
    for (int t0 = 0; t0 < JC; t0 += TJ) {
        __syncthreads();
        const float4* src = &g_rec[(size_t)(j0 + t0) * 10];
#pragma unroll
        for (int t = threadIdx.x, q = 0; q < (TJ * 10) / R_ROWS; q++, t += R_ROWS)
            srec[t] = src[t];
        __syncthreads();

#pragma unroll 2
        for (int jj = 0; jj < TJ; jj++) {
            const ulonglong2* rec = (const ulonglong2*)&srec[jj * 10];
            ulonglong2 w0 = rec[0], w1 = rec[1], w2 = rec[2], w3 = rec[3];
            ulonglong2 w4 = rec[4], w5 = rec[5], w6 = rec[6], w7 = rec[7];
            ulonglong2 w8 = rec[8];
            float cfj = ((const float*)&rec[9])[0];

            float j0f, j1f, j2f, jcf;
            unpack2(w8.x, j0f, j1f);
            unpack2(w8.y, j2f, jcf);

            // row A
            {
                float d = dot32(rpA, w0.x, w0.y, w1.x, w1.y, w2.x, w2.y, w3.x, w3.y,
                                     w4.x, w4.y, w5.x, w5.y, w6.x, w6.y, w7.x, w7.y);
                float sq2 = d + (cfj + cqA);
                float sp2 = fmaf(uA0, j0f, fmaf(uA1, j1f, fmaf(uA2, j2f, cpA + jcf)));
                float eq = ex2f(sq2);
                float ep = ex2f(sp2);
                ull e2 = pack2(eq, ep);
                ZA = f2add(ZA, e2);
                SA = f2fma(e2, e2, SA);
                AA = fmaf(ep, eq, AA);
            }
            // row B
            {
                float d = dot32(rpB, w0.x, w0.y, w1.x, w1.y, w2.x, w2.y, w3.x, w3.y,
                                     w4.x, w4.y, w5.x, w5.y, w6.x, w6.y, w7.x, w7.y);
                float sq2 = d + (cfj + cqB);
                float sp2 = fmaf(uB0, j0f, fmaf(uB1, j1f, fmaf(uB2, j2f, cpB + jcf)));
                float eq = ex2f(sq2);
                float ep = ex2f(sp2);
                ull e2 = pack2(eq, ep);
                ZB = f2add(ZB, e2);
                SB = f2fma(e2, e2, SB);
                AB = fmaf(ep, eq, AB);
            }
        }
    }

    float ZqA, ZpA, CA, BbA; unpack2(ZA, ZqA, ZpA); unpack2(SA, CA, BbA);
    float ZqB, ZpB, CB, BbB; unpack2(ZB, ZqB, ZpB); unpack2(SB, CB, BbB);

    size_t pA = ((size_t)gA * S_CHUNKS + chunk) * 2;
    g_part[pA + 0] = make_float4(ZqA, AA, CA, ZpA);
    g_part[pA + 1] = make_float4(BbA, 0.f, 0.f, 0.f);
    size_t pB = ((size_t)gB * S_CHUNKS + chunk) * 2;
    g_part[pB + 0] = make_float4(ZqB, AB, CB, ZpB);
    g_part[pB + 1] = make_float4(BbB, 0.f, 0.f, 0.f);
}

__global__ void reduce_kernel(const float* __restrict__ weights,
                              float* __restrict__ out, int N)
{
    __shared__ float sred[256];
    int b = blockIdx.x;
    float sum = 0.f;

    for (int i = threadIdx.x; i < N; i += 256) {
        int g = b * N + i;
        float Zq = 0.f, A = 0.f, C = 0.f, Zp = 0.f, Bb = 0.f;
#pragma unroll
        for (int k = 0; k < S_CHUNKS; k++) {
            float4 p0 = g_part[((size_t)g * S_CHUNKS + k) * 2 + 0];
            float4 p1 = g_part[((size_t)g * S_CHUNKS + k) * 2 + 1];
            Zq += p0.x; A += p0.y; C += p0.z; Zp += p0.w; Bb += p1.x;
        }
        float izp = 1.f / Zp, izq = 1.f / Zq;
        float loss = Bb * izp * izp - 2.f * A * izp * izq + C * izq * izq;
        sum = fmaf(weights[g], loss, sum);
    }

    sred[threadIdx.x] = sum;
    __syncthreads();
#pragma unroll
    for (int s = 128; s > 0; s >>= 1) {
        if (threadIdx.x < s) sred[threadIdx.x] += sred[threadIdx.x + s];
        __syncthreads();
    }
    if (threadIdx.x == 0) out[b] = sred[0];
}

extern "C" void kernel_launch(void* const* d_in, const int* in_sizes, int n_in,
                              void* d_out, int out_size)
{
    const float* points  = (const float*)d_in[0];  // [B,N,3]
    const float* fea1    = (const float*)d_in[1];  // [B,N,32]
    const float* fea2    = (const float*)d_in[2];  // [B,N,32]
    const float* weights = (const float*)d_in[3];  // [B,N]

    int BN = in_sizes[3];
    int B  = out_size;
    int N  = BN / B;

    prep_kernel<<<(BN + 63) / 64, 64>>>(points, fea2, BN);

    int rowblks = BN / (R_ROWS * IR);
    main_kernel<<<rowblks * S_CHUNKS, R_ROWS>>>(fea1, points, N);

    reduce_kernel<<<B, 256>>>(weights, (float*)d_out, N);
}

// round 4
// speedup vs baseline: 1.2596x; 1.2596x over previous
#include <cuda_runtime.h>

// DeepFeatureLoss: out[b] = sum_i w[b,i] * sum_j (p_ij - q_ij)^2
//   p = softmax_j over -||x_i/s - x_j/s||^2   (scores <= 0)
//   q = softmax_j over -||f1_i - f2_j||^2     (scores <= 0 -> fixed 2^KSH shift)
// sum_j (p-q)^2 = B/Zp^2 - 2A/(Zp Zq) + C/Zq^2.
// Records pre-scaled by 2*log2e so both exps are bare ex2.approx.
// Main kernel split into two half-range launches (chunk halves) so ncu
// captures it; record read via LDS.128 (10 LDS per j instead of 18).

#define SIGMA_INV 20.0f
#define LOG2E     1.4426950408889634f
#define KSH       44.0f
#define S_CHUNKS  16
#define R_ROWS    128          // threads per block
#define TJ        128
#define MAX_ROWS  16384

// per-j record, 10 float4 (160B):
// [0..7]: 2*log2e*f2 ; [8]: (2L*u0, 2L*u1, 2L*u2, -L*|u|^2) ; [9].x: -L*|f2|^2
static __device__ __align__(16) float4 g_rec[MAX_ROWS * 10];
// per (row, chunk) partial: (Zq, A, C, Zp), (Bb, 0,0,0)
static __device__ __align__(16) float4 g_part[(size_t)MAX_ROWS * S_CHUNKS * 2];

typedef unsigned long long ull;

__device__ __forceinline__ ull f2mul(ull a, ull b) {
    ull d; asm("mul.rn.f32x2 %0, %1, %2;" : "=l"(d) : "l"(a), "l"(b)); return d;
}
__device__ __forceinline__ ull f2fma(ull a, ull b, ull c) {
    ull d; asm("fma.rn.f32x2 %0, %1, %2, %3;" : "=l"(d) : "l"(a), "l"(b), "l"(c)); return d;
}
__device__ __forceinline__ ull f2add(ull a, ull b) {
    ull d; asm("add.rn.f32x2 %0, %1, %2;" : "=l"(d) : "l"(a), "l"(b)); return d;
}
__device__ __forceinline__ float ex2f(float x) {
    float y; asm("ex2.approx.f32 %0, %1;" : "=f"(y) : "f"(x)); return y;
}
__device__ __forceinline__ void unpack2(ull v, float& lo, float& hi) {
    asm("mov.b64 {%0, %1}, %2;" : "=f"(lo), "=f"(hi) : "l"(v));
}
__device__ __forceinline__ ull pack2(float lo, float hi) {
    ull v; asm("mov.b64 %0, {%1, %2};" : "=l"(v) : "f"(lo), "f"(hi)); return v;
}

__global__ void prep_kernel(const float* __restrict__ points,
                            const float* __restrict__ fea2,
                            int BN)
{
    int g = blockIdx.x * blockDim.x + threadIdx.x;
    if (g >= BN) return;

    float4 r[10];
    const float4* f2 = (const float4*)(fea2 + (size_t)g * 32);
    float cf = 0.f;
#pragma unroll
    for (int q = 0; q < 8; q++) {
        float4 v = f2[q];
        cf = fmaf(v.x, v.x, cf); cf = fmaf(v.y, v.y, cf);
        cf = fmaf(v.z, v.z, cf); cf = fmaf(v.w, v.w, cf);
        float s = 2.f * LOG2E;
        r[q] = make_float4(s * v.x, s * v.y, s * v.z, s * v.w);
    }
    float u0 = points[(size_t)g * 3 + 0] * SIGMA_INV;
    float u1 = points[(size_t)g * 3 + 1] * SIGMA_INV;
    float u2 = points[(size_t)g * 3 + 2] * SIGMA_INV;
    float cu = -(u0 * u0 + u1 * u1 + u2 * u2) * LOG2E;
    float s = 2.f * LOG2E;
    r[8] = make_float4(s * u0, s * u1, s * u2, cu);
    r[9] = make_float4(-cf * LOG2E, 0.f, 0.f, 0.f);

#pragma unroll
    for (int q = 0; q < 10; q++) g_rec[(size_t)g * 10 + q] = r[q];
}

__global__ __launch_bounds__(R_ROWS) void main_kernel(
    const float* __restrict__ fea1,
    const float* __restrict__ points,
    int N, int chunk0)
{
    __shared__ __align__(16) float4 srec[TJ * 10];

    const int rowblk = blockIdx.x / (S_CHUNKS / 2);
    const int chunk  = chunk0 + (blockIdx.x % (S_CHUNKS / 2));
    const int g  = rowblk * R_ROWS + threadIdx.x;
    const int b  = g / N;
    const int JC = N / S_CHUNKS;
    const int j0 = b * N + chunk * JC;

    // row constants
    ull rp[16];
    float nf = 0.f;
    {
        const float4* fp = (const float4*)(fea1 + (size_t)g * 32);
#pragma unroll
        for (int q = 0; q < 8; q++) {
            float4 v = fp[q];
            nf = fmaf(v.x, v.x, nf); nf = fmaf(v.y, v.y, nf);
            nf = fmaf(v.z, v.z, nf); nf = fmaf(v.w, v.w, nf);
            rp[2 * q + 0] = pack2(v.x, v.y);
            rp[2 * q + 1] = pack2(v.z, v.w);
        }
    }
    const float cq = KSH - nf * LOG2E;

    float u0 = points[(size_t)g * 3 + 0] * SIGMA_INV;
    float u1 = points[(size_t)g * 3 + 1] * SIGMA_INV;
    float u2 = points[(size_t)g * 3 + 2] * SIGMA_INV;
    const float cp = -(u0 * u0 + u1 * u1 + u2 * u2) * LOG2E;

    ull Z = 0, S = 0;            // (Zq, Zp), (C, Bb)
    float A = 0.f;

#pragma unroll 1
    for (int t0 = 0; t0 < JC; t0 += TJ) {
        __syncthreads();
        const float4* src = &g_rec[(size_t)(j0 + t0) * 10];
#pragma unroll
        for (int t = threadIdx.x, q = 0; q < (TJ * 10) / R_ROWS; q++, t += R_ROWS)
            srec[t] = src[t];
        __syncthreads();

#pragma unroll 2
        for (int jj = 0; jj < TJ; jj++) {
            const ulonglong2* rec = (const ulonglong2*)&srec[jj * 10];
            // 8x LDS.128 feature loads, interleaved with the packed dot
            ulonglong2 p0 = rec[0], p1 = rec[1], p2 = rec[2], p3 = rec[3];
            ull a0 = f2mul(rp[0], p0.x);
            ull a1 = f2mul(rp[1], p0.y);
            ull a2 = f2mul(rp[2], p1.x);
            ull a3 = f2mul(rp[3], p1.y);
            ulonglong2 p4 = rec[4], p5 = rec[5], p6 = rec[6], p7 = rec[7];
            a0 = f2fma(rp[4],  p2.x, a0);
            a1 = f2fma(rp[5],  p2.y, a1);
            a2 = f2fma(rp[6],  p3.x, a2);
            a3 = f2fma(rp[7],  p3.y, a3);
            a0 = f2fma(rp[8],  p4.x, a0);
            a1 = f2fma(rp[9],  p4.y, a1);
            a2 = f2fma(rp[10], p5.x, a2);
            a3 = f2fma(rp[11], p5.y, a3);
            a0 = f2fma(rp[12], p6.x, a0);
            a1 = f2fma(rp[13], p6.y, a1);
            a2 = f2fma(rp[14], p7.x, a2);
            a3 = f2fma(rp[15], p7.y, a3);
            ull ss = f2add(f2add(a0, a1), f2add(a2, a3));
            float lo, hi; unpack2(ss, lo, hi);

            float4 v8 = srec[jj * 10 + 8];          // LDS.128
            float cfj = ((const float*)&srec[jj * 10 + 9])[0];  // LDS.32

            float sq2 = (lo + hi) + (cfj + cq);
            float sp2 = fmaf(u0, v8.x, fmaf(u1, v8.y, fmaf(u2, v8.z, cp + v8.w)));
            float eq = ex2f(sq2);
            float ep = ex2f(sp2);
            ull e2 = pack2(eq, ep);
            Z = f2add(Z, e2);
            S = f2fma(e2, e2, S);
            A = fmaf(ep, eq, A);
        }
    }

    float Zq, Zp, C, Bb;
    unpack2(Z, Zq, Zp);
    unpack2(S, C, Bb);

    size_t p = ((size_t)g * S_CHUNKS + chunk) * 2;
    g_part[p + 0] = make_float4(Zq, A, C, Zp);
    g_part[p + 1] = make_float4(Bb, 0.f, 0.f, 0.f);
}

__global__ void reduce_kernel(const float* __restrict__ weights,
                              float* __restrict__ out, int N)
{
    __shared__ float sred[256];
    int b = blockIdx.x;
    float sum = 0.f;

    for (int i = threadIdx.x; i < N; i += 256) {
        int g = b * N + i;
        float Zq = 0.f, A = 0.f, C = 0.f, Zp = 0.f, Bb = 0.f;
#pragma unroll
        for (int k = 0; k < S_CHUNKS; k++) {
            float4 p0 = g_part[((size_t)g * S_CHUNKS + k) * 2 + 0];
            float4 p1 = g_part[((size_t)g * S_CHUNKS + k) * 2 + 1];
            Zq += p0.x; A += p0.y; C += p0.z; Zp += p0.w; Bb += p1.x;
        }
        float izp = 1.f / Zp, izq = 1.f / Zq;
        float loss = Bb * izp * izp - 2.f * A * izp * izq + C * izq * izq;
        sum = fmaf(weights[g], loss, sum);
    }

    sred[threadIdx.x] = sum;
    __syncthreads();
#pragma unroll
    for (int s = 128; s > 0; s >>= 1) {
        if (threadIdx.x < s) sred[threadIdx.x] += sred[threadIdx.x + s];
        __syncthreads();
    }
    if (threadIdx.x == 0) out[b] = sred[0];
}

extern "C" void kernel_launch(void* const* d_in, const int* in_sizes, int n_in,
                              void* d_out, int out_size)
{
    const float* points  = (const float*)d_in[0];  // [B,N,3]
    const float* fea1    = (const float*)d_in[1];  // [B,N,32]
    const float* fea2    = (const float*)d_in[2];  // [B,N,32]
    const float* weights = (const float*)d_in[3];  // [B,N]

    int BN = in_sizes[3];
    int B  = out_size;
    int N  = BN / B;

    prep_kernel<<<(BN + 63) / 64, 64>>>(points, fea2, BN);

    int rowblks = BN / R_ROWS;
    // two half-range launches so ncu (-s 5 -c 1) lands on a main_kernel instance
    main_kernel<<<rowblks * (S_CHUNKS / 2), R_ROWS>>>(fea1, points, N, 0);
    main_kernel<<<rowblks * (S_CHUNKS / 2), R_ROWS>>>(fea1, points, N, S_CHUNKS / 2);

    reduce_kernel<<<B, 256>>>(weights, (float*)d_out, N);
}

// round 5
// speedup vs baseline: 1.7018x; 1.3510x over previous
#include <cuda_runtime.h>

// DeepFeatureLoss: out[b] = sum_i w[b,i] * sum_j (p_ij - q_ij)^2
//   p = softmax_j over -||x_i/s - x_j/s||^2   (scores <= 0)
//   q = softmax_j over -||f1_i - f2_j||^2     (scores <= 0 -> fixed 2^KSH shift)
// sum_j (p-q)^2 = B/Zp^2 - 2A/(Zp Zq) + C/Zq^2.
// Records pre-scaled by 2*log2e so both exps are bare ex2.approx.
// R5: parallel reduce (64 blocks + atomicAdd) replaces the 86us 2-block tail;
//     main kernel split into 4 quarter launches so ncu -s 5 lands on it.

#define SIGMA_INV 20.0f
#define LOG2E     1.4426950408889634f
#define KSH       44.0f
#define S_CHUNKS  16
#define R_ROWS    128          // threads per block
#define TJ        128
#define MAX_ROWS  16384

// per-j record, 10 float4 (160B):
// [0..7]: 2*log2e*f2 ; [8]: (2L*u0, 2L*u1, 2L*u2, -L*|u|^2) ; [9].x: -L*|f2|^2
static __device__ __align__(16) float4 g_rec[MAX_ROWS * 10];
// per (row, chunk) partial: (Zq, A, C, Zp), (Bb, 0,0,0)
static __device__ __align__(16) float4 g_part[(size_t)MAX_ROWS * S_CHUNKS * 2];

typedef unsigned long long ull;

__device__ __forceinline__ ull f2mul(ull a, ull b) {
    ull d; asm("mul.rn.f32x2 %0, %1, %2;" : "=l"(d) : "l"(a), "l"(b)); return d;
}
__device__ __forceinline__ ull f2fma(ull a, ull b, ull c) {
    ull d; asm("fma.rn.f32x2 %0, %1, %2, %3;" : "=l"(d) : "l"(a), "l"(b), "l"(c)); return d;
}
__device__ __forceinline__ ull f2add(ull a, ull b) {
    ull d; asm("add.rn.f32x2 %0, %1, %2;" : "=l"(d) : "l"(a), "l"(b)); return d;
}
__device__ __forceinline__ float ex2f(float x) {
    float y; asm("ex2.approx.f32 %0, %1;" : "=f"(y) : "f"(x)); return y;
}
__device__ __forceinline__ void unpack2(ull v, float& lo, float& hi) {
    asm("mov.b64 {%0, %1}, %2;" : "=f"(lo), "=f"(hi) : "l"(v));
}
__device__ __forceinline__ ull pack2(float lo, float hi) {
    ull v; asm("mov.b64 %0, {%1, %2};" : "=l"(v) : "f"(lo), "f"(hi)); return v;
}

__global__ void init_kernel(float* out, int B)
{
    if (threadIdx.x < B) out[threadIdx.x] = 0.f;
}

__global__ void prep_kernel(const float* __restrict__ points,
                            const float* __restrict__ fea2,
                            int BN)
{
    int g = blockIdx.x * blockDim.x + threadIdx.x;
    if (g >= BN) return;

    float4 r[10];
    const float4* f2 = (const float4*)(fea2 + (size_t)g * 32);
    float cf = 0.f;
#pragma unroll
    for (int q = 0; q < 8; q++) {
        float4 v = f2[q];
        cf = fmaf(v.x, v.x, cf); cf = fmaf(v.y, v.y, cf);
        cf = fmaf(v.z, v.z, cf); cf = fmaf(v.w, v.w, cf);
        float s = 2.f * LOG2E;
        r[q] = make_float4(s * v.x, s * v.y, s * v.z, s * v.w);
    }
    float u0 = points[(size_t)g * 3 + 0] * SIGMA_INV;
    float u1 = points[(size_t)g * 3 + 1] * SIGMA_INV;
    float u2 = points[(size_t)g * 3 + 2] * SIGMA_INV;
    float cu = -(u0 * u0 + u1 * u1 + u2 * u2) * LOG2E;
    float s = 2.f * LOG2E;
    r[8] = make_float4(s * u0, s * u1, s * u2, cu);
    r[9] = make_float4(-cf * LOG2E, 0.f, 0.f, 0.f);

#pragma unroll
    for (int q = 0; q < 10; q++) g_rec[(size_t)g * 10 + q] = r[q];
}

__global__ __launch_bounds__(R_ROWS) void main_kernel(
    const float* __restrict__ fea1,
    const float* __restrict__ points,
    int N, int chunk0)
{
    __shared__ __align__(16) float4 srec[TJ * 10];

    const int rowblk = blockIdx.x / (S_CHUNKS / 4);
    const int chunk  = chunk0 + (blockIdx.x % (S_CHUNKS / 4));
    const int g  = rowblk * R_ROWS + threadIdx.x;
    const int b  = g / N;
    const int JC = N / S_CHUNKS;
    const int j0 = b * N + chunk * JC;

    // row constants
    ull rp[16];
    float nf = 0.f;
    {
        const float4* fp = (const float4*)(fea1 + (size_t)g * 32);
#pragma unroll
        for (int q = 0; q < 8; q++) {
            float4 v = fp[q];
            nf = fmaf(v.x, v.x, nf); nf = fmaf(v.y, v.y, nf);
            nf = fmaf(v.z, v.z, nf); nf = fmaf(v.w, v.w, nf);
            rp[2 * q + 0] = pack2(v.x, v.y);
            rp[2 * q + 1] = pack2(v.z, v.w);
        }
    }
    const float cq = KSH - nf * LOG2E;

    float u0 = points[(size_t)g * 3 + 0] * SIGMA_INV;
    float u1 = points[(size_t)g * 3 + 1] * SIGMA_INV;
    float u2 = points[(size_t)g * 3 + 2] * SIGMA_INV;
    const float cp = -(u0 * u0 + u1 * u1 + u2 * u2) * LOG2E;

    ull Z = 0, S = 0;            // (Zq, Zp), (C, Bb)
    float A = 0.f;

#pragma unroll 1
    for (int t0 = 0; t0 < JC; t0 += TJ) {
        __syncthreads();
        const float4* src = &g_rec[(size_t)(j0 + t0) * 10];
#pragma unroll
        for (int t = threadIdx.x, q = 0; q < (TJ * 10) / R_ROWS; q++, t += R_ROWS)
            srec[t] = src[t];
        __syncthreads();

#pragma unroll 2
        for (int jj = 0; jj < TJ; jj++) {
            const ulonglong2* rec = (const ulonglong2*)&srec[jj * 10];
            ulonglong2 p0 = rec[0], p1 = rec[1], p2 = rec[2], p3 = rec[3];
            ull a0 = f2mul(rp[0], p0.x);
            ull a1 = f2mul(rp[1], p0.y);
            ull a2 = f2mul(rp[2], p1.x);
            ull a3 = f2mul(rp[3], p1.y);
            ulonglong2 p4 = rec[4], p5 = rec[5], p6 = rec[6], p7 = rec[7];
            a0 = f2fma(rp[4],  p2.x, a0);
            a1 = f2fma(rp[5],  p2.y, a1);
            a2 = f2fma(rp[6],  p3.x, a2);
            a3 = f2fma(rp[7],  p3.y, a3);
            a0 = f2fma(rp[8],  p4.x, a0);
            a1 = f2fma(rp[9],  p4.y, a1);
            a2 = f2fma(rp[10], p5.x, a2);
            a3 = f2fma(rp[11], p5.y, a3);
            a0 = f2fma(rp[12], p6.x, a0);
            a1 = f2fma(rp[13], p6.y, a1);
            a2 = f2fma(rp[14], p7.x, a2);
            a3 = f2fma(rp[15], p7.y, a3);
            ull ss = f2add(f2add(a0, a1), f2add(a2, a3));
            float lo, hi; unpack2(ss, lo, hi);

            float4 v8 = srec[jj * 10 + 8];
            float cfj = ((const float*)&srec[jj * 10 + 9])[0];

            float sq2 = (lo + hi) + (cfj + cq);
            float sp2 = fmaf(u0, v8.x, fmaf(u1, v8.y, fmaf(u2, v8.z, cp + v8.w)));
            float eq = ex2f(sq2);
            float ep = ex2f(sp2);
            ull e2 = pack2(eq, ep);
            Z = f2add(Z, e2);
            S = f2fma(e2, e2, S);
            A = fmaf(ep, eq, A);
        }
    }

    float Zq, Zp, C, Bb;
    unpack2(Z, Zq, Zp);
    unpack2(S, C, Bb);

    size_t p = ((size_t)g * S_CHUNKS + chunk) * 2;
    g_part[p + 0] = make_float4(Zq, A, C, Zp);
    g_part[p + 1] = make_float4(Bb, 0.f, 0.f, 0.f);
}

// one thread per row, 64 blocks; block partial -> atomicAdd into out[b]
__global__ __launch_bounds__(128) void reduce_kernel(
    const float* __restrict__ weights,
    float* __restrict__ out, int N)
{
    __shared__ float sred[128];
    int g = blockIdx.x * 128 + threadIdx.x;
    int b = g / N;

    float Zq = 0.f, A = 0.f, C = 0.f, Zp = 0.f, Bb = 0.f;
    const float4* base = &g_part[(size_t)g * S_CHUNKS * 2];
#pragma unroll
    for (int k = 0; k < S_CHUNKS; k++) {
        float4 p0 = base[2 * k + 0];
        float4 p1 = base[2 * k + 1];
        Zq += p0.x; A += p0.y; C += p0.z; Zp += p0.w; Bb += p1.x;
    }
    float izp = 1.f / Zp, izq = 1.f / Zq;
    float loss = Bb * izp * izp - 2.f * A * izp * izq + C * izq * izq;
    float v = weights[g] * loss;

    // warp then block reduction (all rows in this block share b: 128 | N)
#pragma unroll
    for (int off = 16; off > 0; off >>= 1)
        v += __shfl_down_sync(0xffffffffu, v, off);
    if ((threadIdx.x & 31) == 0) sred[threadIdx.x >> 5] = v;
    __syncthreads();
    if (threadIdx.x == 0) {
        float s = sred[0] + sred[1] + sred[2] + sred[3];
        atomicAdd(&out[b], s);
    }
}

extern "C" void kernel_launch(void* const* d_in, const int* in_sizes, int n_in,
                              void* d_out, int out_size)
{
    const float* points  = (const float*)d_in[0];  // [B,N,3]
    const float* fea1    = (const float*)d_in[1];  // [B,N,32]
    const float* fea2    = (const float*)d_in[2];  // [B,N,32]
    const float* weights = (const float*)d_in[3];  // [B,N]

    int BN = in_sizes[3];
    int B  = out_size;
    int N  = BN / B;

    init_kernel<<<1, 32>>>((float*)d_out, B);
    prep_kernel<<<(BN + 63) / 64, 64>>>(points, fea2, BN);

    int rowblks = BN / R_ROWS;
    int qgrid = rowblks * (S_CHUNKS / 4);
    // 4 quarter launches: launch index 5 (ncu -s 5 -c 1) lands on main_kernel
    main_kernel<<<qgrid, R_ROWS>>>(fea1, points, N, 0);
    main_kernel<<<qgrid, R_ROWS>>>(fea1, points, N, 4);
    main_kernel<<<qgrid, R_ROWS>>>(fea1, points, N, 8);
    main_kernel<<<qgrid, R_ROWS>>>(fea1, points, N, 12);

    reduce_kernel<<<BN / 128, 128>>>(weights, (float*)d_out, N);
}

// round 6
// speedup vs baseline: 2.3551x; 1.3838x over previous
#include <cuda_runtime.h>

// DeepFeatureLoss: out[b] = sum_i w[b,i] * sum_j (p_ij - q_ij)^2
//   p = softmax_j over -||x_i/s - x_j/s||^2   (scores <= 0)
//   q = softmax_j over -||f1_i - f2_j||^2     (scores <= 0 -> fixed 2^KSH shift)
// sum_j (p-q)^2 = B/Zp^2 - 2A/(Zp Zq) + C/Zq^2.
// Records pre-scaled by 2*log2e so both exps are bare ex2.approx.
// R6: single full-grid main launch (1024 blocks -> ~28 warps/SM, was 7);
//     launch order [prep, main, init, reduce] so ncu -s 5 -c 1 lands on main.

#define SIGMA_INV 20.0f
#define LOG2E     1.4426950408889634f
#define KSH       44.0f
#define S_CHUNKS  16
#define R_ROWS    128          // threads per block
#define TJ        128
#define MAX_ROWS  16384

// per-j record, 10 float4 (160B):
// [0..7]: 2*log2e*f2 ; [8]: (2L*u0, 2L*u1, 2L*u2, -L*|u|^2) ; [9].x: -L*|f2|^2
static __device__ __align__(16) float4 g_rec[MAX_ROWS * 10];
// per (row, chunk) partial: (Zq, A, C, Zp), (Bb, 0,0,0)
static __device__ __align__(16) float4 g_part[(size_t)MAX_ROWS * S_CHUNKS * 2];

typedef unsigned long long ull;

__device__ __forceinline__ ull f2mul(ull a, ull b) {
    ull d; asm("mul.rn.f32x2 %0, %1, %2;" : "=l"(d) : "l"(a), "l"(b)); return d;
}
__device__ __forceinline__ ull f2fma(ull a, ull b, ull c) {
    ull d; asm("fma.rn.f32x2 %0, %1, %2, %3;" : "=l"(d) : "l"(a), "l"(b), "l"(c)); return d;
}
__device__ __forceinline__ ull f2add(ull a, ull b) {
    ull d; asm("add.rn.f32x2 %0, %1, %2;" : "=l"(d) : "l"(a), "l"(b)); return d;
}
__device__ __forceinline__ float ex2f(float x) {
    float y; asm("ex2.approx.f32 %0, %1;" : "=f"(y) : "f"(x)); return y;
}
__device__ __forceinline__ void unpack2(ull v, float& lo, float& hi) {
    asm("mov.b64 {%0, %1}, %2;" : "=f"(lo), "=f"(hi) : "l"(v));
}
__device__ __forceinline__ ull pack2(float lo, float hi) {
    ull v; asm("mov.b64 %0, {%1, %2};" : "=l"(v) : "f"(lo), "f"(hi)); return v;
}

__global__ void init_kernel(float* out, int B)
{
    if (threadIdx.x < B) out[threadIdx.x] = 0.f;
}

__global__ void prep_kernel(const float* __restrict__ points,
                            const float* __restrict__ fea2,
                            int BN)
{
    int g = blockIdx.x * blockDim.x + threadIdx.x;
    if (g >= BN) return;

    float4 r[10];
    const float4* f2 = (const float4*)(fea2 + (size_t)g * 32);
    float cf = 0.f;
#pragma unroll
    for (int q = 0; q < 8; q++) {
        float4 v = f2[q];
        cf = fmaf(v.x, v.x, cf); cf = fmaf(v.y, v.y, cf);
        cf = fmaf(v.z, v.z, cf); cf = fmaf(v.w, v.w, cf);
        float s = 2.f * LOG2E;
        r[q] = make_float4(s * v.x, s * v.y, s * v.z, s * v.w);
    }
    float u0 = points[(size_t)g * 3 + 0] * SIGMA_INV;
    float u1 = points[(size_t)g * 3 + 1] * SIGMA_INV;
    float u2 = points[(size_t)g * 3 + 2] * SIGMA_INV;
    float cu = -(u0 * u0 + u1 * u1 + u2 * u2) * LOG2E;
    float s = 2.f * LOG2E;
    r[8] = make_float4(s * u0, s * u1, s * u2, cu);
    r[9] = make_float4(-cf * LOG2E, 0.f, 0.f, 0.f);

#pragma unroll
    for (int q = 0; q < 10; q++) g_rec[(size_t)g * 10 + q] = r[q];
}

__global__ __launch_bounds__(R_ROWS) void main_kernel(
    const float* __restrict__ fea1,
    const float* __restrict__ points,
    int N)
{
    __shared__ __align__(16) float4 srec[TJ * 10];

    const int rowblk = blockIdx.x / S_CHUNKS;
    const int chunk  = blockIdx.x % S_CHUNKS;
    const int g  = rowblk * R_ROWS + threadIdx.x;
    const int b  = g / N;
    const int JC = N / S_CHUNKS;
    const int j0 = b * N + chunk * JC;

    // row constants
    ull rp[16];
    float nf = 0.f;
    {
        const float4* fp = (const float4*)(fea1 + (size_t)g * 32);
#pragma unroll
        for (int q = 0; q < 8; q++) {
            float4 v = fp[q];
            nf = fmaf(v.x, v.x, nf); nf = fmaf(v.y, v.y, nf);
            nf = fmaf(v.z, v.z, nf); nf = fmaf(v.w, v.w, nf);
            rp[2 * q + 0] = pack2(v.x, v.y);
            rp[2 * q + 1] = pack2(v.z, v.w);
        }
    }
    const float cq = KSH - nf * LOG2E;

    float u0 = points[(size_t)g * 3 + 0] * SIGMA_INV;
    float u1 = points[(size_t)g * 3 + 1] * SIGMA_INV;
    float u2 = points[(size_t)g * 3 + 2] * SIGMA_INV;
    const float cp = -(u0 * u0 + u1 * u1 + u2 * u2) * LOG2E;

    ull Z = 0, S = 0;            // (Zq, Zp), (C, Bb)
    float A = 0.f;

#pragma unroll 1
    for (int t0 = 0; t0 < JC; t0 += TJ) {
        __syncthreads();
        const float4* src = &g_rec[(size_t)(j0 + t0) * 10];
#pragma unroll
        for (int t = threadIdx.x, q = 0; q < (TJ * 10) / R_ROWS; q++, t += R_ROWS)
            srec[t] = src[t];
        __syncthreads();

#pragma unroll 2
        for (int jj = 0; jj < TJ; jj++) {
            const ulonglong2* rec = (const ulonglong2*)&srec[jj * 10];
            ulonglong2 p0 = rec[0], p1 = rec[1], p2 = rec[2], p3 = rec[3];
            ull a0 = f2mul(rp[0], p0.x);
            ull a1 = f2mul(rp[1], p0.y);
            ull a2 = f2mul(rp[2], p1.x);
            ull a3 = f2mul(rp[3], p1.y);
            ulonglong2 p4 = rec[4], p5 = rec[5], p6 = rec[6], p7 = rec[7];
            a0 = f2fma(rp[4],  p2.x, a0);
            a1 = f2fma(rp[5],  p2.y, a1);
            a2 = f2fma(rp[6],  p3.x, a2);
            a3 = f2fma(rp[7],  p3.y, a3);
            a0 = f2fma(rp[8],  p4.x, a0);
            a1 = f2fma(rp[9],  p4.y, a1);
            a2 = f2fma(rp[10], p5.x, a2);
            a3 = f2fma(rp[11], p5.y, a3);
            a0 = f2fma(rp[12], p6.x, a0);
            a1 = f2fma(rp[13], p6.y, a1);
            a2 = f2fma(rp[14], p7.x, a2);
            a3 = f2fma(rp[15], p7.y, a3);
            ull ss = f2add(f2add(a0, a1), f2add(a2, a3));
            float lo, hi; unpack2(ss, lo, hi);

            float4 v8 = srec[jj * 10 + 8];
            float cfj = ((const float*)&srec[jj * 10 + 9])[0];

            float sq2 = (lo + hi) + (cfj + cq);
            float sp2 = fmaf(u0, v8.x, fmaf(u1, v8.y, fmaf(u2, v8.z, cp + v8.w)));
            float eq = ex2f(sq2);
            float ep = ex2f(sp2);
            ull e2 = pack2(eq, ep);
            Z = f2add(Z, e2);
            S = f2fma(e2, e2, S);
            A = fmaf(ep, eq, A);
        }
    }

    float Zq, Zp, C, Bb;
    unpack2(Z, Zq, Zp);
    unpack2(S, C, Bb);

    size_t p = ((size_t)g * S_CHUNKS + chunk) * 2;
    g_part[p + 0] = make_float4(Zq, A, C, Zp);
    g_part[p + 1] = make_float4(Bb, 0.f, 0.f, 0.f);
}

// one thread per row; block partial -> atomicAdd into out[b]
__global__ __launch_bounds__(128) void reduce_kernel(
    const float* __restrict__ weights,
    float* __restrict__ out, int N)
{
    __shared__ float sred[4];
    int g = blockIdx.x * 128 + threadIdx.x;
    int b = g / N;

    float Zq = 0.f, A = 0.f, C = 0.f, Zp = 0.f, Bb = 0.f;
    const float4* base = &g_part[(size_t)g * S_CHUNKS * 2];
#pragma unroll
    for (int k = 0; k < S_CHUNKS; k++) {
        float4 p0 = base[2 * k + 0];
        float4 p1 = base[2 * k + 1];
        Zq += p0.x; A += p0.y; C += p0.z; Zp += p0.w; Bb += p1.x;
    }
    float izp = 1.f / Zp, izq = 1.f / Zq;
    float loss = Bb * izp * izp - 2.f * A * izp * izq + C * izq * izq;
    float v = weights[g] * loss;

#pragma unroll
    for (int off = 16; off > 0; off >>= 1)
        v += __shfl_down_sync(0xffffffffu, v, off);
    if ((threadIdx.x & 31) == 0) sred[threadIdx.x >> 5] = v;
    __syncthreads();
    if (threadIdx.x == 0) {
        float s = sred[0] + sred[1] + sred[2] + sred[3];
        atomicAdd(&out[b], s);
    }
}

extern "C" void kernel_launch(void* const* d_in, const int* in_sizes, int n_in,
                              void* d_out, int out_size)
{
    const float* points  = (const float*)d_in[0];  // [B,N,3]
    const float* fea1    = (const float*)d_in[1];  // [B,N,32]
    const float* fea2    = (const float*)d_in[2];  // [B,N,32]
    const float* weights = (const float*)d_in[3];  // [B,N]

    int BN = in_sizes[3];
    int B  = out_size;
    int N  = BN / B;

    // Launch order [prep, main, init, reduce]: 4 launches per call, so global
    // launch index 5 (ncu -s 5 -c 1) = second call's main_kernel (full grid).
    prep_kernel<<<(BN + 63) / 64, 64>>>(points, fea2, BN);

    int rowblks = BN / R_ROWS;
    main_kernel<<<rowblks * S_CHUNKS, R_ROWS>>>(fea1, points, N);

    init_kernel<<<1, 32>>>((float*)d_out, B);

    reduce_kernel<<<BN / 128, 128>>>(weights, (float*)d_out, N);
}

// round 8
// speedup vs baseline: 3.4920x; 1.4828x over previous
#include <cuda_runtime.h>
#include <cuda_bf16.h>
#include <cstdint>

// DeepFeatureLoss via mma.sync.m16n8k16 (bf16 -> fp32 HMMA; compute_103-safe).
// Score matrices in log2 domain, constants folded in as extra K slots:
//   D_feat[i,j] = 2L*f1_i.f2_j - L|f2_j|^2 + (KSH - L|f1_i|^2)
//   D_sp[i,j]   = 2L*u_i.u_j - L|u_i|^2 - L|u_j|^2,  u = x/sigma
// eq = ex2(D_feat), ep = ex2(D_sp);
//   sum_j (p-q)^2 = Bb/Zp^2 - 2A/(Zp Zq) + C/Zq^2
// bf16 split operands: feature 2-split (3 cross terms, K slots 0..95 + 6 const
// slots = 102, 7 k16-steps), spatial 3-split (6 cross terms/coord + 6 const
// slots = 24, 2 k16-steps). fp32 accumulate in registers (no TMEM, no tcgen05).

#define SIGMA_INV 20.0f
#define LOG2E     1.4426950408889634f
#define KSH       44.0f
#define MAX_ROWS  16384
#define JCH       16       // j chunks -> grid = rowtiles * 16
#define MT        128      // rows per block
#define NT        128      // j tile

typedef unsigned long long ull;
typedef unsigned int  u32;
typedef unsigned short u16;

// K-major padded rows:
// feature: 128 halves/row (64 words): slots 0..101 data, rest 0
// spatial:  64 halves/row (32 words): slots 0..23 data, rest 0
static __device__ __align__(16) u16 g_Af[(size_t)MAX_ROWS * 128];
static __device__ __align__(16) u16 g_Bf[(size_t)MAX_ROWS * 128];
static __device__ __align__(16) u16 g_As[(size_t)MAX_ROWS * 64];
static __device__ __align__(16) u16 g_Bs[(size_t)MAX_ROWS * 64];
// per (row, chunk) partials: (Zq, A, C, Zp), (Bb,0,0,0)
static __device__ __align__(16) float4 g_part[(size_t)MAX_ROWS * JCH * 2];

// ---------- helpers ----------
__device__ __forceinline__ ull f2add(ull a, ull b) {
    ull d; asm("add.rn.f32x2 %0, %1, %2;" : "=l"(d) : "l"(a), "l"(b)); return d;
}
__device__ __forceinline__ ull f2fma(ull a, ull b, ull c) {
    ull d; asm("fma.rn.f32x2 %0, %1, %2, %3;" : "=l"(d) : "l"(a), "l"(b), "l"(c)); return d;
}
__device__ __forceinline__ float ex2f(float x) {
    float y; asm("ex2.approx.f32 %0, %1;" : "=f"(y) : "f"(x)); return y;
}
__device__ __forceinline__ void unpack2(ull v, float& lo, float& hi) {
    asm("mov.b64 {%0, %1}, %2;" : "=f"(lo), "=f"(hi) : "l"(v));
}
__device__ __forceinline__ ull pack2(float lo, float hi) {
    ull v; asm("mov.b64 %0, {%1, %2};" : "=l"(v) : "f"(lo), "f"(hi)); return v;
}
__device__ __forceinline__ u16 f2bf(float x) {
    __nv_bfloat16 b = __float2bfloat16(x);
    return *reinterpret_cast<u16*>(&b);
}
__device__ __forceinline__ float bf2f(u16 u) {
    __nv_bfloat16 b = *reinterpret_cast<__nv_bfloat16*>(&u);
    return __bfloat162float(b);
}
__device__ __forceinline__ u32 pk(u16 lo, u16 hi) { return (u32)lo | ((u32)hi << 16); }

// mma.sync m16n8k16 bf16 -> f32, D += A*B
__device__ __forceinline__ void mma16816(float& d0, float& d1, float& d2, float& d3,
                                         const u32* a, u32 b0, u32 b1)
{
    asm("mma.sync.aligned.m16n8k16.row.col.f32.bf16.bf16.f32 "
        "{%0,%1,%2,%3},{%4,%5,%6,%7},{%8,%9},{%0,%1,%2,%3};"
        : "+f"(d0), "+f"(d1), "+f"(d2), "+f"(d3)
        : "r"(a[0]), "r"(a[1]), "r"(a[2]), "r"(a[3]), "r"(b0), "r"(b1));
}

// ---------- prep: build split K-major rows (identical math to prior round) ----------
__global__ void prep_kernel(const float* __restrict__ points,
                            const float* __restrict__ fea1,
                            const float* __restrict__ fea2,
                            int BN)
{
    int g = blockIdx.x * 128 + threadIdx.x;
    if (g >= BN) return;
    const u16 one = f2bf(1.0f);

    // ---- feature ----
    float a[32], bb[32];
    float na = 0.f, nb = 0.f;
    const float4* F1 = (const float4*)(fea1 + (size_t)g * 32);
    const float4* F2 = (const float4*)(fea2 + (size_t)g * 32);
#pragma unroll
    for (int q = 0; q < 8; q++) {
        float4 v = F1[q];
        a[4*q] = v.x; a[4*q+1] = v.y; a[4*q+2] = v.z; a[4*q+3] = v.w;
        na = fmaf(v.x,v.x, fmaf(v.y,v.y, fmaf(v.z,v.z, fmaf(v.w,v.w, na))));
        float4 w = F2[q];
        nb = fmaf(w.x,w.x, fmaf(w.y,w.y, fmaf(w.z,w.z, fmaf(w.w,w.w, nb))));
        float s = 2.f * LOG2E;
        bb[4*q] = s*w.x; bb[4*q+1] = s*w.y; bb[4*q+2] = s*w.z; bb[4*q+3] = s*w.w;
    }
    u16 ah[32], al[32], bh[32], bl[32];
#pragma unroll
    for (int k = 0; k < 32; k++) {
        ah[k] = f2bf(a[k]);  al[k] = f2bf(a[k]  - bf2f(ah[k]));
        bh[k] = f2bf(bb[k]); bl[k] = f2bf(bb[k] - bf2f(bh[k]));
    }
    float cq = KSH - na * LOG2E;
    float cf = -nb * LOG2E;
    u16 cqh = f2bf(cq); float r = cq - bf2f(cqh);
    u16 cqm = f2bf(r);  u16 cql = f2bf(r - bf2f(cqm));
    u16 cfh = f2bf(cf); r = cf - bf2f(cfh);
    u16 cfm = f2bf(r);  u16 cfl = f2bf(r - bf2f(cfm));

    u32* Af = (u32*)&g_Af[(size_t)g * 128];
    u32* Bf = (u32*)&g_Bf[(size_t)g * 128];
#pragma unroll
    for (int k = 0; k < 16; k++) {
        Af[k]      = pk(ah[2*k], ah[2*k+1]);
        Af[16 + k] = pk(al[2*k], al[2*k+1]);
        Af[32 + k] = pk(ah[2*k], ah[2*k+1]);
        Bf[k]      = pk(bh[2*k], bh[2*k+1]);
        Bf[16 + k] = pk(bh[2*k], bh[2*k+1]);
        Bf[32 + k] = pk(bl[2*k], bl[2*k+1]);
    }
    // slots 96..98: 1 * (cfh,cfm,cfl)  |  99..101: (cqh,cqm,cql) * 1
    Af[48] = pk(one, one); Af[49] = pk(one, cqh); Af[50] = pk(cqm, cql);
    Bf[48] = pk(cfh, cfm); Bf[49] = pk(cfl, one); Bf[50] = pk(one, one);
#pragma unroll
    for (int k = 51; k < 64; k++) { Af[k] = 0; Bf[k] = 0; }

    // ---- spatial ----
    float u0 = points[(size_t)g*3+0] * SIGMA_INV;
    float u1 = points[(size_t)g*3+1] * SIGMA_INV;
    float u2 = points[(size_t)g*3+2] * SIGMA_INV;
    float uu[3] = {u0, u1, u2};
    float nsp = u0*u0 + u1*u1 + u2*u2;
    float ci = -nsp * LOG2E;
    u16 uh[3], um[3], ul[3], vh[3], vm[3], vl[3];
#pragma unroll
    for (int c = 0; c < 3; c++) {
        float x = uu[c];
        uh[c] = f2bf(x); float r1 = x - bf2f(uh[c]);
        um[c] = f2bf(r1); ul[c] = f2bf(r1 - bf2f(um[c]));
        float y = 2.f * LOG2E * x;
        vh[c] = f2bf(y); float r2 = y - bf2f(vh[c]);
        vm[c] = f2bf(r2); vl[c] = f2bf(r2 - bf2f(vm[c]));
    }
    u16 cih = f2bf(ci); float r3 = ci - bf2f(cih);
    u16 cim = f2bf(r3); u16 cil = f2bf(r3 - bf2f(cim));

    u16 ta[24], tb[24];
#pragma unroll
    for (int c = 0; c < 3; c++) {
        ta[c]    = uh[c]; tb[c]    = vh[c];
        ta[3+c]  = uh[c]; tb[3+c]  = vm[c];
        ta[6+c]  = um[c]; tb[6+c]  = vh[c];
        ta[9+c]  = uh[c]; tb[9+c]  = vl[c];
        ta[12+c] = ul[c]; tb[12+c] = vh[c];
        ta[15+c] = um[c]; tb[15+c] = vm[c];
        ta[21+c] = one;
        tb[18+c] = one;
    }
    ta[18] = cih; ta[19] = cim; ta[20] = cil;
    tb[21] = cih; tb[22] = cim; tb[23] = cil;

    u32* As = (u32*)&g_As[(size_t)g * 64];
    u32* Bs = (u32*)&g_Bs[(size_t)g * 64];
#pragma unroll
    for (int w = 0; w < 12; w++) {
        As[w] = pk(ta[2*w], ta[2*w+1]);
        Bs[w] = pk(tb[2*w], tb[2*w+1]);
    }
#pragma unroll
    for (int w = 12; w < 32; w++) { As[w] = 0; Bs[w] = 0; }
}

// ---------- main: HMMA + register epilogue ----------
// B staged in smem with word-rotate swizzle (w + 4*(n&7)) mod rowwords:
// conflict-free for both b0 (kp=t+8ks) and b1 (kp=t+4+8ks) fragment loads.
__global__ __launch_bounds__(128) void main_kernel(int N)
{
    __shared__ __align__(16) u32 sBf[128 * 64];
    __shared__ __align__(16) u32 sBs[128 * 32];

    const int tid = threadIdx.x;
    const int w = tid >> 5, l = tid & 31, g = l >> 2, t = l & 3;
    const int rowtile = blockIdx.x >> 4;
    const int chunk   = blockIdx.x & 15;
    const int rowbase = rowtile * MT;
    const int b  = rowbase / N;
    const int jc = N / JCH;               // 256
    const int j0 = b * N + chunk * jc;
    const int ntiles = jc / NT;           // 2

    const u32* Af = (const u32*)g_Af;
    const u32* As = (const u32*)g_As;

    // A fragments (held for whole kernel)
    u32 af[2][7][4], asp[2][2][4];
#pragma unroll
    for (int rt = 0; rt < 2; rt++) {
        int r0 = rowbase + 32 * w + 16 * rt + g;
#pragma unroll
        for (int ks = 0; ks < 7; ks++) {
            af[rt][ks][0] = Af[(size_t)r0 * 64 + t + 8 * ks];
            af[rt][ks][1] = Af[(size_t)(r0 + 8) * 64 + t + 8 * ks];
            af[rt][ks][2] = Af[(size_t)r0 * 64 + t + 4 + 8 * ks];
            af[rt][ks][3] = Af[(size_t)(r0 + 8) * 64 + t + 4 + 8 * ks];
        }
#pragma unroll
        for (int ks = 0; ks < 2; ks++) {
            asp[rt][ks][0] = As[(size_t)r0 * 32 + t + 8 * ks];
            asp[rt][ks][1] = As[(size_t)(r0 + 8) * 32 + t + 8 * ks];
            asp[rt][ks][2] = As[(size_t)r0 * 32 + t + 4 + 8 * ks];
            asp[rt][ks][3] = As[(size_t)(r0 + 8) * 32 + t + 4 + 8 * ks];
        }
    }

    ull Z[4] = {0,0,0,0}, S[4] = {0,0,0,0};
    float Aa[4] = {0.f, 0.f, 0.f, 0.f};

    for (int jt = 0; jt < ntiles; jt++) {
        __syncthreads();
        const int jrow = j0 + jt * NT;
        // stage feature B (128 rows x 64 words), swizzled
        const float4* srcF = (const float4*)&g_Bf[(size_t)jrow * 128];
#pragma unroll
        for (int i = 0; i < 16; i++) {
            int W4 = tid + i * 128;
            int n = W4 >> 4, w0 = (W4 & 15) * 4;
            float4 v = srcF[W4];
            int dst = n * 64 + ((w0 + 4 * (n & 7)) & 63);
            *(float4*)&sBf[dst] = v;
        }
        // stage spatial B (128 rows x 32 words), swizzled
        const float4* srcS = (const float4*)&g_Bs[(size_t)jrow * 64];
#pragma unroll
        for (int i = 0; i < 8; i++) {
            int W4 = tid + i * 128;
            int n = W4 >> 3, w0 = (W4 & 7) * 4;
            float4 v = srcS[W4];
            int dst = n * 32 + ((w0 + 4 * (n & 7)) & 31);
            *(float4*)&sBs[dst] = v;
        }
        __syncthreads();

#pragma unroll 1
        for (int ns = 0; ns < 16; ns++) {
            const int n = ns * 8 + g;
            const u32* rowF = &sBf[n * 64];
            const u32* rowS = &sBs[n * 32];
            u32 fb0[7], fb1[7], sb0[2], sb1[2];
            const int rot = 4 * g;   // n & 7 == g
#pragma unroll
            for (int ks = 0; ks < 7; ks++) {
                fb0[ks] = rowF[(t + 8 * ks + rot) & 63];
                fb1[ks] = rowF[(t + 4 + 8 * ks + rot) & 63];
            }
#pragma unroll
            for (int ks = 0; ks < 2; ks++) {
                sb0[ks] = rowS[(t + 8 * ks + rot) & 31];
                sb1[ks] = rowS[(t + 4 + 8 * ks + rot) & 31];
            }
#pragma unroll
            for (int rt = 0; rt < 2; rt++) {
                float d0 = 0.f, d1 = 0.f, d2 = 0.f, d3 = 0.f;
#pragma unroll
                for (int ks = 0; ks < 7; ks++)
                    mma16816(d0, d1, d2, d3, af[rt][ks], fb0[ks], fb1[ks]);
                float e0 = 0.f, e1 = 0.f, e2 = 0.f, e3 = 0.f;
#pragma unroll
                for (int ks = 0; ks < 2; ks++)
                    mma16816(e0, e1, e2, e3, asp[rt][ks], sb0[ks], sb1[ks]);

                // epilogue: c0,c1 -> row g (ctx 2rt); c2,c3 -> row g+8 (ctx 2rt+1)
                {
                    float eqa = ex2f(d0), epa = ex2f(e0);
                    float eqb = ex2f(d1), epb = ex2f(e1);
                    ull ea = pack2(eqa, epa), eb = pack2(eqb, epb);
                    int c = rt * 2;
                    Z[c] = f2add(Z[c], ea); Z[c] = f2add(Z[c], eb);
                    S[c] = f2fma(ea, ea, S[c]); S[c] = f2fma(eb, eb, S[c]);
                    Aa[c] = fmaf(epa, eqa, Aa[c]); Aa[c] = fmaf(epb, eqb, Aa[c]);
                }
                {
                    float eqa = ex2f(d2), epa = ex2f(e2);
                    float eqb = ex2f(d3), epb = ex2f(e3);
                    ull ea = pack2(eqa, epa), eb = pack2(eqb, epb);
                    int c = rt * 2 + 1;
                    Z[c] = f2add(Z[c], ea); Z[c] = f2add(Z[c], eb);
                    S[c] = f2fma(ea, ea, S[c]); S[c] = f2fma(eb, eb, S[c]);
                    Aa[c] = fmaf(epa, eqa, Aa[c]); Aa[c] = fmaf(epb, eqb, Aa[c]);
                }
            }
        }
    }

    // quad-reduce (lanes t=0..3 of each group hold different columns of same rows)
#pragma unroll
    for (int c = 0; c < 4; c++) {
        float Zq, Zp, C, Bb;
        unpack2(Z[c], Zq, Zp);
        unpack2(S[c], C, Bb);
        float A_ = Aa[c];
#pragma unroll
        for (int m = 1; m <= 2; m <<= 1) {
            Zq += __shfl_xor_sync(0xffffffffu, Zq, m);
            Zp += __shfl_xor_sync(0xffffffffu, Zp, m);
            C  += __shfl_xor_sync(0xffffffffu, C,  m);
            Bb += __shfl_xor_sync(0xffffffffu, Bb, m);
            A_ += __shfl_xor_sync(0xffffffffu, A_, m);
        }
        if (t == 0) {
            int row = rowbase + 32 * w + 16 * (c >> 1) + 8 * (c & 1) + g;
            size_t p = ((size_t)row * JCH + chunk) * 2;
            g_part[p + 0] = make_float4(Zq, A_, C, Zp);
            g_part[p + 1] = make_float4(Bb, 0.f, 0.f, 0.f);
        }
    }
}

// ---------- init / reduce ----------
__global__ void init_kernel(float* out, int B)
{
    if (threadIdx.x < B) out[threadIdx.x] = 0.f;
}

__global__ __launch_bounds__(128) void reduce_kernel(
    const float* __restrict__ weights,
    float* __restrict__ out, int N)
{
    __shared__ float sred[4];
    int g = blockIdx.x * 128 + threadIdx.x;
    int b = g / N;

    float Zq = 0.f, A = 0.f, C = 0.f, Zp = 0.f, Bb = 0.f;
    const float4* base = &g_part[(size_t)g * JCH * 2];
#pragma unroll
    for (int k = 0; k < JCH; k++) {
        float4 p0 = base[2 * k + 0];
        float4 p1 = base[2 * k + 1];
        Zq += p0.x; A += p0.y; C += p0.z; Zp += p0.w; Bb += p1.x;
    }
    float izp = 1.f / Zp, izq = 1.f / Zq;
    float loss = Bb * izp * izp - 2.f * A * izp * izq + C * izq * izq;
    float v = weights[g] * loss;

#pragma unroll
    for (int off = 16; off > 0; off >>= 1)
        v += __shfl_down_sync(0xffffffffu, v, off);
    if ((threadIdx.x & 31) == 0) sred[threadIdx.x >> 5] = v;
    __syncthreads();
    if (threadIdx.x == 0) {
        float s = sred[0] + sred[1] + sred[2] + sred[3];
        atomicAdd(&out[b], s);
    }
}

extern "C" void kernel_launch(void* const* d_in, const int* in_sizes, int n_in,
                              void* d_out, int out_size)
{
    const float* points  = (const float*)d_in[0];  // [B,N,3]
    const float* fea1    = (const float*)d_in[1];  // [B,N,32]
    const float* fea2    = (const float*)d_in[2];  // [B,N,32]
    const float* weights = (const float*)d_in[3];  // [B,N]

    int BN = in_sizes[3];
    int B  = out_size;
    int N  = BN / B;

    // Launch order [prep, main, init, reduce]: launch index 5 (ncu -s 5 -c 1)
    // = second call's main_kernel.
    prep_kernel<<<(BN + 127) / 128, 128>>>(points, fea1, fea2, BN);

    int rowtiles = BN / MT;                       // 64
    main_kernel<<<rowtiles * JCH, 128>>>(N);      // 1024 blocks

    init_kernel<<<1, 32>>>((float*)d_out, B);
    reduce_kernel<<<BN / 128, 128>>>(weights, (float*)d_out, N);
}

// round 9
// speedup vs baseline: 3.7421x; 1.0716x over previous
#include <cuda_runtime.h>
#include <cuda_bf16.h>
#include <cstdint>

// DeepFeatureLoss via mma.sync.m16n8k16 bf16 HMMA (feature dot only) +
// fp32 scalar spatial score in the epilogue.
//   D_feat raw = 2L*f1_i.f2_j (3-term bf16 split, 96 K-slots = 6 k16 steps)
//   score_q = D + cf_j + cq_i   (cf_j = -L|f2_j|^2 fp32; cq_i = KSH - L|f1_i|^2)
//   score_p = u_i . w_j + ci_i + cs_j   (w_j = 2L*u_j, c = -L|u|^2, u = x/sigma)
//   eq = ex2(score_q), ep = ex2(score_p)
//   sum_j (p-q)^2 = Bb/Zp^2 - 2A/(Zp Zq) + C/Zq^2
// Row constants (cq_i, ci_i) cancel in the ratios; they only guard range.

#define SIGMA_INV 20.0f
#define LOG2E     1.4426950408889634f
#define KSH       44.0f
#define MAX_ROWS  16384
#define JCH       8
#define MT        128
#define NT        128

typedef unsigned long long ull;
typedef unsigned int  u32;
typedef unsigned short u16;

// feature split rows, K-major, 64 u32 words stride (words 0..47 used):
// A: [0..15]=ah, [16..31]=al, [32..47]=ah ; B: [0..15]=bh, [16..31]=bh, [32..47]=bl
static __device__ __align__(16) u16 g_Af[(size_t)MAX_ROWS * 128];
static __device__ __align__(16) u16 g_Bf[(size_t)MAX_ROWS * 128];
static __device__ __align__(16) float4 g_vj[MAX_ROWS];   // (2L*u0,2L*u1,2L*u2, -L|u|^2)
static __device__ float  g_cf[MAX_ROWS];                  // -L|f2|^2
static __device__ float  g_rc[MAX_ROWS];                  // KSH - L|f1|^2
static __device__ __align__(16) float4 g_part[(size_t)MAX_ROWS * JCH * 2];

// ---------- helpers ----------
__device__ __forceinline__ ull f2add(ull a, ull b) {
    ull d; asm("add.rn.f32x2 %0, %1, %2;" : "=l"(d) : "l"(a), "l"(b)); return d;
}
__device__ __forceinline__ ull f2fma(ull a, ull b, ull c) {
    ull d; asm("fma.rn.f32x2 %0, %1, %2, %3;" : "=l"(d) : "l"(a), "l"(b), "l"(c)); return d;
}
__device__ __forceinline__ float ex2f(float x) {
    float y; asm("ex2.approx.f32 %0, %1;" : "=f"(y) : "f"(x)); return y;
}
__device__ __forceinline__ void unpack2(ull v, float& lo, float& hi) {
    asm("mov.b64 {%0, %1}, %2;" : "=f"(lo), "=f"(hi) : "l"(v));
}
__device__ __forceinline__ ull pack2(float lo, float hi) {
    ull v; asm("mov.b64 %0, {%1, %2};" : "=l"(v) : "f"(lo), "f"(hi)); return v;
}
__device__ __forceinline__ u16 f2bf(float x) {
    __nv_bfloat16 b = __float2bfloat16(x);
    return *reinterpret_cast<u16*>(&b);
}
__device__ __forceinline__ float bf2f(u16 u) {
    __nv_bfloat16 b = *reinterpret_cast<__nv_bfloat16*>(&u);
    return __bfloat162float(b);
}
__device__ __forceinline__ u32 pk(u16 lo, u16 hi) { return (u32)lo | ((u32)hi << 16); }

__device__ __forceinline__ void mma16816(float& d0, float& d1, float& d2, float& d3,
                                         const u32* a, u32 b0, u32 b1)
{
    asm("mma.sync.aligned.m16n8k16.row.col.f32.bf16.bf16.f32 "
        "{%0,%1,%2,%3},{%4,%5,%6,%7},{%8,%9},{%0,%1,%2,%3};"
        : "+f"(d0), "+f"(d1), "+f"(d2), "+f"(d3)
        : "r"(a[0]), "r"(a[1]), "r"(a[2]), "r"(a[3]), "r"(b0), "r"(b1));
}

// ---------- prep: 2 threads per row (side 0: A/f1, side 1: B/f2 + spatial) ----------
__global__ void prep_kernel(const float* __restrict__ points,
                            const float* __restrict__ fea1,
                            const float* __restrict__ fea2,
                            int BN)
{
    int idx = blockIdx.x * 128 + threadIdx.x;
    int g = idx >> 1, side = idx & 1;
    if (g >= BN) return;

    if (side == 0) {
        float a[32]; float na = 0.f;
        const float4* F1 = (const float4*)(fea1 + (size_t)g * 32);
#pragma unroll
        for (int q = 0; q < 8; q++) {
            float4 v = F1[q];
            a[4*q] = v.x; a[4*q+1] = v.y; a[4*q+2] = v.z; a[4*q+3] = v.w;
            na = fmaf(v.x,v.x, fmaf(v.y,v.y, fmaf(v.z,v.z, fmaf(v.w,v.w, na))));
        }
        u16 ah[32], al[32];
#pragma unroll
        for (int k = 0; k < 32; k++) {
            ah[k] = f2bf(a[k]); al[k] = f2bf(a[k] - bf2f(ah[k]));
        }
        u32* Af = (u32*)&g_Af[(size_t)g * 128];
#pragma unroll
        for (int k = 0; k < 16; k++) {
            u32 h = pk(ah[2*k], ah[2*k+1]);
            Af[k] = h;
            Af[16 + k] = pk(al[2*k], al[2*k+1]);
            Af[32 + k] = h;
        }
        g_rc[g] = KSH - na * LOG2E;
    } else {
        float bb[32]; float nb = 0.f;
        const float4* F2 = (const float4*)(fea2 + (size_t)g * 32);
#pragma unroll
        for (int q = 0; q < 8; q++) {
            float4 w = F2[q];
            nb = fmaf(w.x,w.x, fmaf(w.y,w.y, fmaf(w.z,w.z, fmaf(w.w,w.w, nb))));
            float s = 2.f * LOG2E;
            bb[4*q] = s*w.x; bb[4*q+1] = s*w.y; bb[4*q+2] = s*w.z; bb[4*q+3] = s*w.w;
        }
        u16 bh[32], bl[32];
#pragma unroll
        for (int k = 0; k < 32; k++) {
            bh[k] = f2bf(bb[k]); bl[k] = f2bf(bb[k] - bf2f(bh[k]));
        }
        u32* Bf = (u32*)&g_Bf[(size_t)g * 128];
#pragma unroll
        for (int k = 0; k < 16; k++) {
            u32 h = pk(bh[2*k], bh[2*k+1]);
            Bf[k] = h;
            Bf[16 + k] = h;
            Bf[32 + k] = pk(bl[2*k], bl[2*k+1]);
        }
        g_cf[g] = -nb * LOG2E;

        float u0 = points[(size_t)g*3+0] * SIGMA_INV;
        float u1 = points[(size_t)g*3+1] * SIGMA_INV;
        float u2 = points[(size_t)g*3+2] * SIGMA_INV;
        float s = 2.f * LOG2E;
        g_vj[g] = make_float4(s*u0, s*u1, s*u2,
                              -(u0*u0 + u1*u1 + u2*u2) * LOG2E);
    }
}

// ---------- main ----------
__global__ __launch_bounds__(128) void main_kernel(int N)
{
    __shared__ __align__(16) u32 sBf[128 * 64];
    __shared__ __align__(16) float4 sVj[128];
    __shared__ float sCf[128];

    const int tid = threadIdx.x;
    const int w = tid >> 5, l = tid & 31, g = l >> 2, t = l & 3;
    const int rowtile = blockIdx.x >> 3;        // / JCH
    const int chunk   = blockIdx.x & 7;
    const int rowbase = rowtile * MT;
    const int b  = rowbase / N;
    const int jc = N / JCH;                     // 512
    const int j0 = b * N + chunk * jc;
    const int ntiles = jc / NT;                 // 4

    const u32* Af = (const u32*)g_Af;

    // A fragments for 6 k-steps, 2 row-tiles
    u32 af[2][6][4];
#pragma unroll
    for (int rt = 0; rt < 2; rt++) {
        int r0 = rowbase + 32 * w + 16 * rt + g;
#pragma unroll
        for (int ks = 0; ks < 6; ks++) {
            af[rt][ks][0] = Af[(size_t)r0 * 64 + t + 8 * ks];
            af[rt][ks][1] = Af[(size_t)(r0 + 8) * 64 + t + 8 * ks];
            af[rt][ks][2] = Af[(size_t)r0 * 64 + t + 4 + 8 * ks];
            af[rt][ks][3] = Af[(size_t)(r0 + 8) * 64 + t + 4 + 8 * ks];
        }
    }
    // row constants: h = 2rt + (0: row g, 1: row g+8)
    float ui0[4], ui1[4], ui2[4], ci4[4], cq4[4];
#pragma unroll
    for (int h = 0; h < 4; h++) {
        int r = rowbase + 32 * w + 16 * (h >> 1) + 8 * (h & 1) + g;
        float4 v = g_vj[r];
        const float inv2L = 0.5f / LOG2E;
        ui0[h] = v.x * inv2L; ui1[h] = v.y * inv2L; ui2[h] = v.z * inv2L;
        ci4[h] = v.w;
        cq4[h] = g_rc[r];
    }

    ull Z[4] = {0,0,0,0}, S[4] = {0,0,0,0};
    float Aa[4] = {0.f, 0.f, 0.f, 0.f};

    for (int jt = 0; jt < ntiles; jt++) {
        __syncthreads();
        const int jrow = j0 + jt * NT;
        // stage feature B rows (48 words each), word-rotate swizzle
        const float4* srcF = (const float4*)&g_Bf[(size_t)jrow * 128];
#pragma unroll
        for (int i = 0; i < 12; i++) {
            int W4 = tid + i * 128;              // 0..1535
            int n = W4 / 12, w0 = (W4 - n * 12) * 4;
            float4 v = srcF[(size_t)n * 16 + (w0 >> 2)];
            int dst = n * 64 + ((w0 + 4 * (n & 7)) & 63);
            *(float4*)&sBf[dst] = v;
        }
        sVj[tid] = g_vj[jrow + tid];
        sCf[tid] = g_cf[jrow + tid];
        __syncthreads();

#pragma unroll 1
        for (int ns = 0; ns < 16; ns++) {
            const int n = ns * 8 + g;
            const u32* rowF = &sBf[n * 64];
            const int rot = 4 * g;
            u32 fb0[6], fb1[6];
#pragma unroll
            for (int ks = 0; ks < 6; ks++) {
                fb0[ks] = rowF[(t + 8 * ks + rot) & 63];
                fb1[ks] = rowF[(t + 4 + 8 * ks + rot) & 63];
            }
            const int c0 = ns * 8 + 2 * t;
            float4 vA = sVj[c0];
            float4 vB = sVj[c0 + 1];
            float2 cf2 = *(const float2*)&sCf[c0];

#pragma unroll
            for (int rt = 0; rt < 2; rt++) {
                float d0 = 0.f, d1 = 0.f, d2 = 0.f, d3 = 0.f;
#pragma unroll
                for (int ks = 0; ks < 6; ks++)
                    mma16816(d0, d1, d2, d3, af[rt][ks], fb0[ks], fb1[ks]);

                const int h0 = 2 * rt, h1 = 2 * rt + 1;
                // (d0: h0/colA) (d1: h0/colB) (d2: h1/colA) (d3: h1/colB)
                {
                    float sq = d0 + (cf2.x + cq4[h0]);
                    float sp = fmaf(ui0[h0], vA.x, fmaf(ui1[h0], vA.y,
                               fmaf(ui2[h0], vA.z, ci4[h0] + vA.w)));
                    float eq = ex2f(sq), ep = ex2f(sp);
                    ull e = pack2(eq, ep);
                    Z[h0] = f2add(Z[h0], e); S[h0] = f2fma(e, e, S[h0]);
                    Aa[h0] = fmaf(ep, eq, Aa[h0]);
                }
                {
                    float sq = d1 + (cf2.y + cq4[h0]);
                    float sp = fmaf(ui0[h0], vB.x, fmaf(ui1[h0], vB.y,
                               fmaf(ui2[h0], vB.z, ci4[h0] + vB.w)));
                    float eq = ex2f(sq), ep = ex2f(sp);
                    ull e = pack2(eq, ep);
                    Z[h0] = f2add(Z[h0], e); S[h0] = f2fma(e, e, S[h0]);
                    Aa[h0] = fmaf(ep, eq, Aa[h0]);
                }
                {
                    float sq = d2 + (cf2.x + cq4[h1]);
                    float sp = fmaf(ui0[h1], vA.x, fmaf(ui1[h1], vA.y,
                               fmaf(ui2[h1], vA.z, ci4[h1] + vA.w)));
                    float eq = ex2f(sq), ep = ex2f(sp);
                    ull e = pack2(eq, ep);
                    Z[h1] = f2add(Z[h1], e); S[h1] = f2fma(e, e, S[h1]);
                    Aa[h1] = fmaf(ep, eq, Aa[h1]);
                }
                {
                    float sq = d3 + (cf2.y + cq4[h1]);
                    float sp = fmaf(ui0[h1], vB.x, fmaf(ui1[h1], vB.y,
                               fmaf(ui2[h1], vB.z, ci4[h1] + vB.w)));
                    float eq = ex2f(sq), ep = ex2f(sp);
                    ull e = pack2(eq, ep);
                    Z[h1] = f2add(Z[h1], e); S[h1] = f2fma(e, e, S[h1]);
                    Aa[h1] = fmaf(ep, eq, Aa[h1]);
                }
            }
        }
    }

    // quad-reduce over t and write partials
#pragma unroll
    for (int h = 0; h < 4; h++) {
        float Zq, Zp, C, Bb;
        unpack2(Z[h], Zq, Zp);
        unpack2(S[h], C, Bb);
        float A_ = Aa[h];
#pragma unroll
        for (int m = 1; m <= 2; m <<= 1) {
            Zq += __shfl_xor_sync(0xffffffffu, Zq, m);
            Zp += __shfl_xor_sync(0xffffffffu, Zp, m);
            C  += __shfl_xor_sync(0xffffffffu, C,  m);
            Bb += __shfl_xor_sync(0xffffffffu, Bb, m);
            A_ += __shfl_xor_sync(0xffffffffu, A_, m);
        }
        if (t == 0) {
            int row = rowbase + 32 * w + 16 * (h >> 1) + 8 * (h & 1) + g;
            size_t p = ((size_t)row * JCH + chunk) * 2;
            g_part[p + 0] = make_float4(Zq, A_, C, Zp);
            g_part[p + 1] = make_float4(Bb, 0.f, 0.f, 0.f);
        }
    }
}

// ---------- init / reduce ----------
__global__ void init_kernel(float* out, int B)
{
    if (threadIdx.x < B) out[threadIdx.x] = 0.f;
}

// 4 threads per row; 32 rows per block
__global__ __launch_bounds__(128) void reduce_kernel(
    const float* __restrict__ weights,
    float* __restrict__ out, int N)
{
    __shared__ float sred[4];
    const int tid = threadIdx.x;
    const int r = blockIdx.x * 32 + (tid >> 2);
    const int t = tid & 3;
    const int b = (blockIdx.x * 32) / N;

    const float4* base = &g_part[(size_t)r * JCH * 2];
    float4 p0 = base[2 * t + 0],       p1 = base[2 * t + 1];
    float4 p2 = base[2 * (t + 4) + 0], p3 = base[2 * (t + 4) + 1];
    float Zq = p0.x + p2.x, A = p0.y + p2.y, C = p0.z + p2.z;
    float Zp = p0.w + p2.w, Bb = p1.x + p3.x;

#pragma unroll
    for (int m = 1; m <= 2; m <<= 1) {
        Zq += __shfl_xor_sync(0xffffffffu, Zq, m);
        Zp += __shfl_xor_sync(0xffffffffu, Zp, m);
        C  += __shfl_xor_sync(0xffffffffu, C,  m);
        Bb += __shfl_xor_sync(0xffffffffu, Bb, m);
        A  += __shfl_xor_sync(0xffffffffu, A,  m);
    }
    float v = 0.f;
    if (t == 0) {
        float izp = 1.f / Zp, izq = 1.f / Zq;
        float loss = Bb * izp * izp - 2.f * A * izp * izq + C * izq * izq;
        v = weights[r] * loss;
    }
#pragma unroll
    for (int off = 16; off > 0; off >>= 1)
        v += __shfl_down_sync(0xffffffffu, v, off);
    if ((tid & 31) == 0) sred[tid >> 5] = v;
    __syncthreads();
    if (tid == 0) {
        atomicAdd(&out[b], sred[0] + sred[1] + sred[2] + sred[3]);
    }
}

extern "C" void kernel_launch(void* const* d_in, const int* in_sizes, int n_in,
                              void* d_out, int out_size)
{
    const float* points  = (const float*)d_in[0];  // [B,N,3]
    const float* fea1    = (const float*)d_in[1];  // [B,N,32]
    const float* fea2    = (const float*)d_in[2];  // [B,N,32]
    const float* weights = (const float*)d_in[3];  // [B,N]

    int BN = in_sizes[3];
    int B  = out_size;
    int N  = BN / B;

    prep_kernel<<<(2 * BN + 127) / 128, 128>>>(points, fea1, fea2, BN);

    int rowtiles = BN / MT;                     // 64
    main_kernel<<<rowtiles * JCH, 128>>>(N);    // 512 blocks

    init_kernel<<<1, 32>>>((float*)d_out, B);
    reduce_kernel<<<BN / 32, 128>>>(weights, (float*)d_out, N);
}